// round 1
// baseline (speedup 1.0000x reference)
#include <cuda_runtime.h>
#include <cstdint>

#define B_      2
#define I_      1024
#define J_      1024
#define C_      64
#define TJ      64
#define NT      (J_/TJ)
#define ROWS    8
#define THREADS 128

__device__ __forceinline__ float tanh_apx(float x) {
    float y;
    asm("tanh.approx.f32 %0, %1;" : "=f"(y) : "f"(x));
    return y;
}
__device__ __forceinline__ void cp16(uint32_t s, const void* g) {
    asm volatile("cp.async.cg.shared.global [%0], [%1], 16;" :: "r"(s), "l"(g));
}
__device__ __forceinline__ void cp_commit() { asm volatile("cp.async.commit_group;"); }
template<int N> __device__ __forceinline__ void cp_wait() {
    asm volatile("cp.async.wait_group %0;" :: "n"(N));
}

__global__ __launch_bounds__(THREADS)
void fused_attn_mlp_kernel(const float* __restrict__ Q,
                           const float* __restrict__ K,
                           const float* __restrict__ bias,
                           const float* __restrict__ mask,
                           float* __restrict__ out,      // [B,I,C]
                           float* __restrict__ attn)     // [B,I,J]
{
    __shared__ __align__(16) float4 kbuf[2][TJ * 16];   // 2 x 16KB K tiles
    __shared__ __align__(16) float  sbias[C_];          // 0.5*bias
    __shared__ __align__(16) float  albuf[ROWS][TJ];    // attn logits staging

    const int tid  = threadIdx.x;
    const int lane = tid & 31;
    const int w    = tid >> 5;
    const int g    = lane >> 4;        // 0/1: which row within warp
    const int lg   = lane & 15;        // lane within row group
    const int rl   = w * 2 + g;        // local row 0..7
    const int row  = blockIdx.x * ROWS + rl;   // global row = b*I + i
    const int b    = row >> 10;
    const int c0   = lg * 4;

    if (tid < C_) sbias[tid] = 0.5f * bias[tid];
    __syncthreads();

    // ssum = 0.5 * sum(bias)  (once per thread; trivial)
    float ssum = 0.f;
    #pragma unroll
    for (int c = 0; c < C_; ++c) ssum += sbias[c];

    const float4 q  = *(const float4*)(Q + (size_t)row * C_ + c0);
    const float4 qh = make_float4(0.5f*q.x, 0.5f*q.y, 0.5f*q.z, 0.5f*q.w);
    const float4 bh = *(const float4*)(&sbias[c0]);

    const float* mrow = mask + (size_t)row * J_;
    const float4* Kb  = (const float4*)K + (size_t)b * J_ * (C_/4);

    float4 acc  = make_float4(0.f, 0.f, 0.f, 0.f);
    float  msum = 0.f;

    const uint32_t sb0 = (uint32_t)__cvta_generic_to_shared(&kbuf[0][0]);
    const uint32_t sb1 = (uint32_t)__cvta_generic_to_shared(&kbuf[1][0]);

    // prefetch tile 0
    {
        const float4* src = Kb;
        #pragma unroll
        for (int r = 0; r < (TJ*16)/THREADS; ++r)
            cp16(sb0 + (uint32_t)(tid + r*THREADS) * 16, src + tid + r*THREADS);
        cp_commit();
    }

    for (int t = 0; t < NT; ++t) {
        if (t + 1 < NT) {
            const float4* src = Kb + (size_t)(t+1) * TJ * 16;
            uint32_t dst = ((t + 1) & 1) ? sb1 : sb0;
            #pragma unroll
            for (int r = 0; r < (TJ*16)/THREADS; ++r)
                cp16(dst + (uint32_t)(tid + r*THREADS) * 16, src + tid + r*THREADS);
            cp_commit();
            cp_wait<1>();
        } else {
            cp_wait<0>();
        }
        __syncthreads();

        const float4* kb  = kbuf[t & 1];
        const float*  mrt = mrow + t * TJ;
        const int     j0  = t * TJ;

        #pragma unroll 4
        for (int jj4 = 0; jj4 < TJ/4; ++jj4) {
            const float4 mv = *(const float4*)(mrt + jj4 * 4);
            const float mm[4] = {mv.x, mv.y, mv.z, mv.w};
            #pragma unroll
            for (int u = 0; u < 4; ++u) {
                const int jj = jj4 * 4 + u;
                const float4 k = kb[jj * 16 + lg];
                const float  m = mm[u];
                // h = 0.5*(q*k + bias)
                float h0 = fmaf(qh.x, k.x, bh.x);
                float h1 = fmaf(qh.y, k.y, bh.y);
                float h2 = fmaf(qh.z, k.z, bh.z);
                float h3 = fmaf(qh.w, k.w, bh.w);
                float hs = (h0 + h1) + (h2 + h3);
                // sigmoid contribution folded: acc += tanh(h) * (m/2); +0.5*msum added at end
                const float mh = 0.5f * m;
                acc.x = fmaf(tanh_apx(h0), mh, acc.x);
                acc.y = fmaf(tanh_apx(h1), mh, acc.y);
                acc.z = fmaf(tanh_apx(h2), mh, acc.z);
                acc.w = fmaf(tanh_apx(h3), mh, acc.w);
                // dot(Q,K) = 2*(sum_c h - sum_c bh); reduce over the 16 lanes of this row
                hs += __shfl_xor_sync(0xffffffffu, hs, 1);
                hs += __shfl_xor_sync(0xffffffffu, hs, 2);
                hs += __shfl_xor_sync(0xffffffffu, hs, 4);
                hs += __shfl_xor_sync(0xffffffffu, hs, 8);
                if (lg == 0) albuf[rl][jj] = (2.0f * (hs - ssum)) * m;
                msum += m;
            }
        }
        __syncthreads();

        // coalesced flush of attention logits for this tile
        {
            const int fr = tid >> 4;           // 0..7
            const int fc = (tid & 15) * 4;     // 0..60
            const float4 v = *(const float4*)(&albuf[fr][fc]);
            const int frow = blockIdx.x * ROWS + fr;
            *(float4*)(attn + (size_t)frow * J_ + j0 + fc) = v;
        }
    }

    // epilogue: output = (acc + 0.5*msum) / msum
    acc.x += 0.5f * msum;
    acc.y += 0.5f * msum;
    acc.z += 0.5f * msum;
    acc.w += 0.5f * msum;
    const float inv = __fdividef(1.0f, msum);
    float4 o = make_float4(acc.x * inv, acc.y * inv, acc.z * inv, acc.w * inv);
    *(float4*)(out + (size_t)row * C_ + c0) = o;
}

extern "C" void kernel_launch(void* const* d_in, const int* in_sizes, int n_in,
                              void* d_out, int out_size) {
    const float* Q    = (const float*)d_in[0];
    const float* K    = (const float*)d_in[1];
    const float* bias = (const float*)d_in[2];
    const float* mask = (const float*)d_in[3];
    float* out  = (float*)d_out;                       // [B,I,C] first
    float* attn = (float*)d_out + (size_t)B_*I_*C_;    // [B,I,J] second

    dim3 grid(B_ * I_ / ROWS);
    dim3 block(THREADS);
    fused_attn_mlp_kernel<<<grid, block>>>(Q, K, bias, mask, out, attn);
}

// round 2
// speedup vs baseline: 2.2164x; 2.2164x over previous
#include <cuda_runtime.h>
#include <cstdint>

#define B_      2
#define I_      1024
#define J_      1024
#define C_      64
#define TJ      64          // j-tile (2 warp-iters per tile)
#define NT      (J_/TJ)     // 16
#define ROWS    4           // rows per block = warps per block
#define THREADS (ROWS*32)
#define KPAD    17          // float4 per K row in smem (padded from 16 -> conflict-free)

__device__ __forceinline__ float tanh_apx(float x) {
    float y;
    asm("tanh.approx.f32 %0, %1;" : "=f"(y) : "f"(x));
    return y;
}
__device__ __forceinline__ void cp16(uint32_t s, const void* g) {
    asm volatile("cp.async.cg.shared.global [%0], [%1], 16;" :: "r"(s), "l"(g));
}
__device__ __forceinline__ void cp_commit() { asm volatile("cp.async.commit_group;"); }
template<int N> __device__ __forceinline__ void cp_wait() {
    asm volatile("cp.async.wait_group %0;" :: "n"(N));
}

__global__ __launch_bounds__(THREADS)
void fused_attn_mlp_kernel(const float* __restrict__ Q,
                           const float* __restrict__ K,
                           const float* __restrict__ bias,
                           const float* __restrict__ mask,
                           float* __restrict__ out,      // [B,I,C]
                           float* __restrict__ attn)     // [B,I,J]
{
    __shared__ __align__(16) float4 kbuf[2][TJ * KPAD];  // 2 x ~17.4KB
    __shared__ __align__(16) float4 sq[ROWS][16];        // 0.5*Q row
    __shared__ __align__(16) float4 sb[16];              // 0.5*bias

    const int tid  = threadIdx.x;
    const int lane = tid & 31;
    const int w    = tid >> 5;          // warp = local row
    const int row  = blockIdx.x * ROWS + w;
    const int b    = (blockIdx.x * ROWS) >> 10;

    // stage 0.5*bias and 0.5*Q rows
    if (tid < C_) ((float*)sb)[tid] = 0.5f * bias[tid];
    #pragma unroll
    for (int idx = tid; idx < ROWS * C_; idx += THREADS) {
        int r = idx >> 6, c = idx & 63;
        ((float*)sq)[idx] = 0.5f * Q[(size_t)(blockIdx.x * ROWS + r) * C_ + c];
    }

    const uint32_t sbase0 = (uint32_t)__cvta_generic_to_shared(&kbuf[0][0]);
    const uint32_t sbase1 = (uint32_t)__cvta_generic_to_shared(&kbuf[1][0]);
    const float4* Kb = (const float4*)K + (size_t)b * J_ * 16;

    // prefetch tile 0 (64 rows x 16 chunks = 1024 cp16, 8 passes of 128 thr)
    {
        #pragma unroll
        for (int p = 0; p < (TJ * 16) / THREADS; ++p) {
            int idx = tid + p * THREADS;
            int r = idx >> 4, c = idx & 15;
            cp16(sbase0 + (uint32_t)(r * KPAD + c) * 16, Kb + (size_t)r * 16 + c);
        }
        cp_commit();
    }
    __syncthreads();

    float ssum = 0.f;
    #pragma unroll
    for (int c = 0; c < C_; ++c) ssum += ((const float*)sb)[c];

    float4 acc[16];
    #pragma unroll
    for (int c = 0; c < 16; ++c) acc[c] = make_float4(0.f, 0.f, 0.f, 0.f);
    float msum = 0.f;

    const float* mrow = mask + (size_t)row * J_;
    float*       arow = attn + (size_t)row * J_;

    for (int t = 0; t < NT; ++t) {
        // prefetch masks for this tile (independent of smem)
        float mj[TJ / 32];
        #pragma unroll
        for (int u = 0; u < TJ / 32; ++u)
            mj[u] = mrow[t * TJ + u * 32 + lane];

        if (t + 1 < NT) {
            const float4* src = Kb + (size_t)(t + 1) * TJ * 16;
            uint32_t dst = ((t + 1) & 1) ? sbase1 : sbase0;
            #pragma unroll
            for (int p = 0; p < (TJ * 16) / THREADS; ++p) {
                int idx = tid + p * THREADS;
                int r = idx >> 4, c = idx & 15;
                cp16(dst + (uint32_t)(r * KPAD + c) * 16, src + (size_t)r * 16 + c);
            }
            cp_commit();
            cp_wait<1>();
        } else {
            cp_wait<0>();
        }
        __syncthreads();

        const float4* kb = kbuf[t & 1];

        #pragma unroll
        for (int u = 0; u < TJ / 32; ++u) {
            const int jj = u * 32 + lane;
            const float4* kr = kb + jj * KPAD;
            const float m  = mj[u];
            const float mh = 0.5f * m;
            float hs0 = 0.f, hs1 = 0.f, hs2 = 0.f, hs3 = 0.f;
            #pragma unroll
            for (int c = 0; c < 16; ++c) {
                const float4 k4 = kr[c];
                const float4 q4 = sq[w][c];
                const float4 b4 = sb[c];
                const float h0 = fmaf(q4.x, k4.x, b4.x);
                const float h1 = fmaf(q4.y, k4.y, b4.y);
                const float h2 = fmaf(q4.z, k4.z, b4.z);
                const float h3 = fmaf(q4.w, k4.w, b4.w);
                hs0 += h0; hs1 += h1; hs2 += h2; hs3 += h3;
                acc[c].x = fmaf(tanh_apx(h0), mh, acc[c].x);
                acc[c].y = fmaf(tanh_apx(h1), mh, acc[c].y);
                acc[c].z = fmaf(tanh_apx(h2), mh, acc[c].z);
                acc[c].w = fmaf(tanh_apx(h3), mh, acc[c].w);
            }
            const float hs = (hs0 + hs1) + (hs2 + hs3);
            arow[t * TJ + jj] = 2.0f * (hs - ssum) * m;
            msum += m;
        }
        __syncthreads();   // compute done before next-next cp.async overwrites
    }

    // one-time warp butterfly reduction of acc[64] + msum
    #pragma unroll
    for (int s = 1; s < 32; s <<= 1) {
        msum += __shfl_xor_sync(0xffffffffu, msum, s);
        #pragma unroll
        for (int c = 0; c < 16; ++c) {
            acc[c].x += __shfl_xor_sync(0xffffffffu, acc[c].x, s);
            acc[c].y += __shfl_xor_sync(0xffffffffu, acc[c].y, s);
            acc[c].z += __shfl_xor_sync(0xffffffffu, acc[c].z, s);
            acc[c].w += __shfl_xor_sync(0xffffffffu, acc[c].w, s);
        }
    }
    if (lane == 0) {
        const float half_m = 0.5f * msum;
        const float inv = __fdividef(1.0f, msum);
        float* orow = out + (size_t)row * C_;
        #pragma unroll
        for (int c = 0; c < 16; ++c) {
            float4 o;
            o.x = (acc[c].x + half_m) * inv;
            o.y = (acc[c].y + half_m) * inv;
            o.z = (acc[c].z + half_m) * inv;
            o.w = (acc[c].w + half_m) * inv;
            *(float4*)(orow + c * 4) = o;
        }
    }
}

extern "C" void kernel_launch(void* const* d_in, const int* in_sizes, int n_in,
                              void* d_out, int out_size) {
    const float* Q    = (const float*)d_in[0];
    const float* K    = (const float*)d_in[1];
    const float* bias = (const float*)d_in[2];
    const float* mask = (const float*)d_in[3];
    float* out  = (float*)d_out;                       // [B,I,C] first
    float* attn = (float*)d_out + (size_t)B_*I_*C_;    // [B,I,J] second

    dim3 grid(B_ * I_ / ROWS);
    dim3 block(THREADS);
    fused_attn_mlp_kernel<<<grid, block>>>(Q, K, bias, mask, out, attn);
}